// round 16
// baseline (speedup 1.0000x reference)
#include <cuda_runtime.h>
#include <cuda_fp16.h>
#include <cstdint>

#define N_NODES_C 50000
#define N_EDGES_C 800000

#define TPB_N 256          // node kernel: 8 warps
#define TPB_E 384          // edge kernel: 12 warps
#define NW_E 12
#define N_WT_EDGE (N_EDGES_C / 16)          // 50000 warp-tiles
#define N_WT_NODE (N_NODES_C / 16)          // 3125 warp-tiles

// Per-node layer-1 partials, fp16x2-packed (cols 2c,2c+1 per uint32; 64 u32/row)
// g_Ph additionally has mb1 folded in: Ph = fp16(P + b1)
__device__ uint32_t g_Ph[(size_t)N_NODES_C * 64];
__device__ uint32_t g_Qh[(size_t)N_NODES_C * 64];

// ---------------- edge kernel SMEM (bytes): 1-pass fp16, nc-pair packed ----
#define OFF_W1 0                          // kc=2, ncp=8 : 8192
#define OFF_W2 8192                       // kc=8, ncp=8 : 32768
#define OFF_W3 40960                      // kc=8, ncp=4 : 16384
#define OFF_B2 57344                      // 128 f32
#define OFF_B3 57856                      // 64 f32
#define OFF_SC 58112                      // 12 warps * 1088 u32 (PQ staging only)
#define PQ_STRIDE_U32 68                  // 64 u32 data + 4 pad (mod 32 == 4)
#define SC_WARP_U32 1088                  // 16 x 68
#define EDGE_SMEM_BYTES (OFF_SC + NW_E*SC_WARP_U32*4)   // 110336

// ---------------- fused node kernel SMEM (bytes): 2-pass (accuracy) --------
#define NOFF_BP  0
#define NOFF_BQ  49152
#define NOFF_BU1 81920
#define NOFF_BU2 131072
#define NOFF_UB1 163840
#define NOFF_UB2 164352
#define NOFF_MB1 164608                   // mb1 (128 f32) for folding into P
#define NODEF_SMEM_BYTES (165120)

// pack two floats into fp16x2 (low half = first arg)
static __device__ __forceinline__ uint32_t hpack2(float x0, float x1) {
    uint32_t r;
    asm("cvt.rn.f16x2.f32 %0, %1, %2;" : "=r"(r) : "f"(x1), "f"(x0));
    return r;
}
static __device__ __forceinline__ float2 hunpack2(uint32_t v) {
    __half2 h = *reinterpret_cast<__half2*>(&v);
    return __half22float2(h);
}
static __device__ __forceinline__ uint32_t hadd2u(uint32_t a, uint32_t b) {
    uint32_t r;
    asm("add.f16x2 %0, %1, %2;" : "=r"(r) : "r"(a), "r"(b));
    return r;
}
// fp16 split of a float pair -> hi fp16x2 + residual-lo fp16x2
static __device__ __forceinline__ void hsplit2(float x0, float x1,
                                               uint32_t& hi, uint32_t& lo) {
    uint32_t h = hpack2(x0, x1);
    __half2 hh = *reinterpret_cast<__half2*>(&h);
    float r0 = x0 - __half2float(__low2half(hh));
    float r1 = x1 - __half2float(__high2half(hh));
    lo = hpack2(r0, r1);
    hi = h;
}

// D += A(16x16 fp16) * B(16x8 fp16), fp32 accum
static __device__ __forceinline__ void mma_f16(float* d, const uint32_t* a,
                                               uint32_t b0, uint32_t b1) {
    asm volatile("mma.sync.aligned.m16n8k16.row.col.f32.f16.f16.f32 "
        "{%0,%1,%2,%3}, {%4,%5,%6,%7}, {%8,%9}, {%0,%1,%2,%3};"
        : "+f"(d[0]), "+f"(d[1]), "+f"(d[2]), "+f"(d[3])
        : "r"(a[0]), "r"(a[1]), "r"(a[2]), "r"(a[3]), "r"(b0), "r"(b1));
}
// 2-pass weight-split MMA (node kernel): Ch += A*Bh ; Cl += A*Bl
static __device__ __forceinline__ void mma2s(float* Ch, float* Cl,
                                             const uint32_t* a, uint4 bw) {
    mma_f16(Ch, a, bw.x, bw.y);
    mma_f16(Cl, a, bw.z, bw.w);
}

// 2-pass fragment staging (node kernel): uint4 = {b0h,b1h,b0l,b1l} per nc
#define STAGE_FRAGS2(dst_off, KC, NC, KROW_EXPR, SRC_PTR, SRC_N, STRIDE)        \
    for (int idx = tid; idx < (KC) * (NC) * 32; idx += (STRIDE)) {              \
        int T = idx & 31, nc = (idx >> 5) % (NC), kc = idx / ((NC) * 32);       \
        int n = nc * 8 + (T >> 2);                                              \
        int k0 = kc * 16 + (T & 3) * 2;                                         \
        int ka = (KROW_EXPR(k0)), kb = (KROW_EXPR(k0 + 1));                     \
        int kd = (KROW_EXPR(k0 + 8)), ke = (KROW_EXPR(k0 + 9));                 \
        float w00 = (SRC_PTR)[ka * (SRC_N) + n], w01 = (SRC_PTR)[kb * (SRC_N) + n]; \
        float w10 = (SRC_PTR)[kd * (SRC_N) + n], w11 = (SRC_PTR)[ke * (SRC_N) + n]; \
        uint32_t b0h, b0l, b1h, b1l;                                            \
        hsplit2(w00, w01, b0h, b0l);                                            \
        hsplit2(w10, w11, b1h, b1l);                                            \
        *(uint4*)(smem + (dst_off) + idx * 16) = make_uint4(b0h, b1h, b0l, b1l); \
    }

// 1-pass fragment staging (edge kernel): uint4 packs TWO adjacent nc
#define STAGE_FRAGS1(dst_off, KC, NCP, KROW_EXPR, SRC_PTR, SRC_N, STRIDE)       \
    for (int idx = tid; idx < (KC) * (NCP) * 32; idx += (STRIDE)) {             \
        int T = idx & 31, p = (idx >> 5) % (NCP), kc = idx / ((NCP) * 32);      \
        int n0 = (2 * p) * 8 + (T >> 2);                                        \
        int n1 = n0 + 8;                                                        \
        int k0 = kc * 16 + (T & 3) * 2;                                         \
        int ka = (KROW_EXPR(k0)), kb = (KROW_EXPR(k0 + 1));                     \
        int kd = (KROW_EXPR(k0 + 8)), ke = (KROW_EXPR(k0 + 9));                 \
        uint32_t a0 = hpack2((SRC_PTR)[ka * (SRC_N) + n0], (SRC_PTR)[kb * (SRC_N) + n0]); \
        uint32_t a1 = hpack2((SRC_PTR)[kd * (SRC_N) + n0], (SRC_PTR)[ke * (SRC_N) + n0]); \
        uint32_t c0 = hpack2((SRC_PTR)[ka * (SRC_N) + n1], (SRC_PTR)[kb * (SRC_N) + n1]); \
        uint32_t c1 = hpack2((SRC_PTR)[kd * (SRC_N) + n1], (SRC_PTR)[ke * (SRC_N) + n1]); \
        *(uint4*)(smem + (dst_off) + idx * 16) = make_uint4(a0, a1, c0, c1);    \
    }

#define KR_ID(k)    (k)
#define KR_W1E(k)   (128 + (k))
#define KR_P(k)     ((k) < 64 ? (k) : (k) + 96)
#define KR_Q(k)     (64 + (k))

// ---------------------------------------------------------------------------
// Fused node kernel (R15 + mb1 folded into g_Ph)
// ---------------------------------------------------------------------------
__global__ __launch_bounds__(TPB_N, 1)
void node_fused_kernel(const float* __restrict__ nf,
                       const float* __restrict__ stx,
                       const float* __restrict__ mW1,
                       const float* __restrict__ mb1,
                       const float* __restrict__ uW1, const float* __restrict__ ub1,
                       const float* __restrict__ uW2, const float* __restrict__ ub2,
                       float* __restrict__ out_node,
                       float* __restrict__ agg)
{
    extern __shared__ char smem[];
    const int tid  = threadIdx.x;
    const int w    = tid >> 5;
    const int lane = tid & 31;
    const int m    = lane & 3;
    const int qrow = lane >> 2;

    STAGE_FRAGS2(NOFF_BP,  6, 16, KR_P,  mW1, 128, TPB_N)
    STAGE_FRAGS2(NOFF_BQ,  4, 16, KR_Q,  mW1, 128, TPB_N)
    STAGE_FRAGS2(NOFF_BU1, 6, 16, KR_ID, uW1, 128, TPB_N)
    STAGE_FRAGS2(NOFF_BU2, 8, 8,  KR_ID, uW2, 64,  TPB_N)
    float* ub1s = (float*)(smem + NOFF_UB1);
    float* ub2s = (float*)(smem + NOFF_UB2);
    float* mb1s = (float*)(smem + NOFF_MB1);
    if (tid < 128) { ub1s[tid] = ub1[tid]; mb1s[tid] = mb1[tid]; }
    if (tid < 64)  ub2s[tid] = ub2[tid];
    __syncthreads();

    const int gw = blockIdx.x * 8 + w;
    const int gstride = gridDim.x * 8;
    const float4 z4 = make_float4(0.f, 0.f, 0.f, 0.f);

    for (int wt = gw; wt < N_WT_NODE; wt += gstride) {
        const int n0 = wt * 16 + qrow;
        const int n1 = n0 + 8;

        #pragma unroll
        for (int s = lane; s < 256; s += 32) {
            int r = s >> 4, q = s & 15;
            *(float4*)(agg + (size_t)(wt * 16 + r) * 64 + q * 4) = z4;
        }

        uint32_t xA[6][4];
        #pragma unroll
        for (int kc = 0; kc < 4; kc++) {
            float2 v0  = __ldg((const float2*)(nf + (size_t)n0 * 64 + kc * 16 + 2 * m));
            float2 v1  = __ldg((const float2*)(nf + (size_t)n1 * 64 + kc * 16 + 2 * m));
            float2 v0b = __ldg((const float2*)(nf + (size_t)n0 * 64 + kc * 16 + 8 + 2 * m));
            float2 v1b = __ldg((const float2*)(nf + (size_t)n1 * 64 + kc * 16 + 8 + 2 * m));
            xA[kc][0] = hpack2(v0.x, v0.y);
            xA[kc][1] = hpack2(v1.x, v1.y);
            xA[kc][2] = hpack2(v0b.x, v0b.y);
            xA[kc][3] = hpack2(v1b.x, v1b.y);
        }
        #pragma unroll
        for (int kc = 4; kc < 6; kc++) {
            int c = (kc - 4) * 16;
            float2 v0  = __ldg((const float2*)(stx + (size_t)n0 * 32 + c + 2 * m));
            float2 v1  = __ldg((const float2*)(stx + (size_t)n1 * 32 + c + 2 * m));
            float2 v0b = __ldg((const float2*)(stx + (size_t)n0 * 32 + c + 8 + 2 * m));
            float2 v1b = __ldg((const float2*)(stx + (size_t)n1 * 32 + c + 8 + 2 * m));
            xA[kc][0] = hpack2(v0.x, v0.y);
            xA[kc][1] = hpack2(v1.x, v1.y);
            xA[kc][2] = hpack2(v0b.x, v0b.y);
            xA[kc][3] = hpack2(v1b.x, v1b.y);
        }

        {   // P (K=96) + mb1 -> fp16x2 packed
            #pragma unroll
            for (int np = 0; np < 8; np++) {
                float2 bA = *(const float2*)(mb1s + np * 8 + 2 * m);
                float2 bB = *(const float2*)(mb1s + (np + 8) * 8 + 2 * m);
                float C0h[4] = {0,0,0,0}, C0l[4] = {0,0,0,0};
                float C1h[4] = {0,0,0,0}, C1l[4] = {0,0,0,0};
                #pragma unroll
                for (int kc = 0; kc < 6; kc++) {
                    uint4 b0 = *(const uint4*)(smem + NOFF_BP + (((kc * 16 + np) * 32) + lane) * 16);
                    uint4 b1 = *(const uint4*)(smem + NOFF_BP + (((kc * 16 + np + 8) * 32) + lane) * 16);
                    mma2s(C0h, C0l, xA[kc], b0);
                    mma2s(C1h, C1l, xA[kc], b1);
                }
                g_Ph[(size_t)n0 * 64 + np * 4 + m] = hpack2(C0h[0] + C0l[0] + bA.x, C0h[1] + C0l[1] + bA.y);
                g_Ph[(size_t)n1 * 64 + np * 4 + m] = hpack2(C0h[2] + C0l[2] + bA.x, C0h[3] + C0l[3] + bA.y);
                g_Ph[(size_t)n0 * 64 + (np + 8) * 4 + m] = hpack2(C1h[0] + C1l[0] + bB.x, C1h[1] + C1l[1] + bB.y);
                g_Ph[(size_t)n1 * 64 + (np + 8) * 4 + m] = hpack2(C1h[2] + C1l[2] + bB.x, C1h[3] + C1l[3] + bB.y);
            }
        }
        {   // Q (K=64) -> fp16x2 packed
            #pragma unroll
            for (int np = 0; np < 8; np++) {
                float C0h[4] = {0,0,0,0}, C0l[4] = {0,0,0,0};
                float C1h[4] = {0,0,0,0}, C1l[4] = {0,0,0,0};
                #pragma unroll
                for (int kc = 0; kc < 4; kc++) {
                    uint4 b0 = *(const uint4*)(smem + NOFF_BQ + (((kc * 16 + np) * 32) + lane) * 16);
                    uint4 b1 = *(const uint4*)(smem + NOFF_BQ + (((kc * 16 + np + 8) * 32) + lane) * 16);
                    mma2s(C0h, C0l, xA[kc], b0);
                    mma2s(C1h, C1l, xA[kc], b1);
                }
                g_Qh[(size_t)n0 * 64 + np * 4 + m] = hpack2(C0h[0] + C0l[0], C0h[1] + C0l[1]);
                g_Qh[(size_t)n1 * 64 + np * 4 + m] = hpack2(C0h[2] + C0l[2], C0h[3] + C0l[3]);
                g_Qh[(size_t)n0 * 64 + (np + 8) * 4 + m] = hpack2(C1h[0] + C1l[0], C1h[1] + C1l[1]);
                g_Qh[(size_t)n1 * 64 + (np + 8) * 4 + m] = hpack2(C1h[2] + C1l[2], C1h[3] + C1l[3]);
            }
        }
        uint32_t A2[8][4];
        {   // h = relu(x@uW1 + ub1)
            #pragma unroll
            for (int j = 0; j < 8; j++) {
                float2 ba = *(const float2*)(ub1s + (2 * j) * 8 + 2 * m);
                float2 bb = *(const float2*)(ub1s + (2 * j + 1) * 8 + 2 * m);
                float Cah[4] = {ba.x, ba.y, ba.x, ba.y}, Cal[4] = {0,0,0,0};
                float Cbh[4] = {bb.x, bb.y, bb.x, bb.y}, Cbl[4] = {0,0,0,0};
                #pragma unroll
                for (int kc = 0; kc < 6; kc++) {
                    uint4 ba4 = *(const uint4*)(smem + NOFF_BU1 + (((kc * 16 + 2 * j) * 32) + lane) * 16);
                    uint4 bb4 = *(const uint4*)(smem + NOFF_BU1 + (((kc * 16 + 2 * j + 1) * 32) + lane) * 16);
                    mma2s(Cah, Cal, xA[kc], ba4);
                    mma2s(Cbh, Cbl, xA[kc], bb4);
                }
                A2[j][0] = hpack2(fmaxf(Cah[0] + Cal[0], 0.f), fmaxf(Cah[1] + Cal[1], 0.f));
                A2[j][1] = hpack2(fmaxf(Cah[2] + Cal[2], 0.f), fmaxf(Cah[3] + Cal[3], 0.f));
                A2[j][2] = hpack2(fmaxf(Cbh[0] + Cbl[0], 0.f), fmaxf(Cbh[1] + Cbl[1], 0.f));
                A2[j][3] = hpack2(fmaxf(Cbh[2] + Cbl[2], 0.f), fmaxf(Cbh[3] + Cbl[3], 0.f));
            }
        }
        {   // out = nf + h@uW2 + ub2
            #pragma unroll
            for (int np = 0; np < 4; np++) {
                float2 b0v = *(const float2*)(ub2s + np * 8 + 2 * m);
                float2 b1v = *(const float2*)(ub2s + (np + 4) * 8 + 2 * m);
                float C0h[4] = {b0v.x, b0v.y, b0v.x, b0v.y}, C0l[4] = {0,0,0,0};
                float C1h[4] = {b1v.x, b1v.y, b1v.x, b1v.y}, C1l[4] = {0,0,0,0};
                #pragma unroll
                for (int kc = 0; kc < 8; kc++) {
                    uint4 b0 = *(const uint4*)(smem + NOFF_BU2 + (((kc * 8 + np) * 32) + lane) * 16);
                    uint4 b1 = *(const uint4*)(smem + NOFF_BU2 + (((kc * 8 + np + 4) * 32) + lane) * 16);
                    mma2s(C0h, C0l, A2[kc], b0);
                    mma2s(C1h, C1l, A2[kc], b1);
                }
                float2 r00 = __ldg((const float2*)(nf + (size_t)n0 * 64 + np * 8 + 2 * m));
                float2 r10 = __ldg((const float2*)(nf + (size_t)n1 * 64 + np * 8 + 2 * m));
                float2 r01 = __ldg((const float2*)(nf + (size_t)n0 * 64 + (np + 4) * 8 + 2 * m));
                float2 r11 = __ldg((const float2*)(nf + (size_t)n1 * 64 + (np + 4) * 8 + 2 * m));
                *(float2*)(out_node + (size_t)n0 * 64 + np * 8 + 2 * m) =
                    make_float2(r00.x + C0h[0] + C0l[0], r00.y + C0h[1] + C0l[1]);
                *(float2*)(out_node + (size_t)n1 * 64 + np * 8 + 2 * m) =
                    make_float2(r10.x + C0h[2] + C0l[2], r10.y + C0h[3] + C0l[3]);
                *(float2*)(out_node + (size_t)n0 * 64 + (np + 4) * 8 + 2 * m) =
                    make_float2(r01.x + C1h[0] + C1l[0], r01.y + C1h[1] + C1l[1]);
                *(float2*)(out_node + (size_t)n1 * 64 + (np + 4) * 8 + 2 * m) =
                    make_float2(r11.x + C1h[2] + C1l[2], r11.y + C1h[3] + C1l[3]);
            }
        }
    }
}

// ---------------------------------------------------------------------------
// Edge kernel: 12 warps, 1-pass fp16 weights, fp16 PQ (hadd2 staging),
// register-direct float2 atomic scatter (no msg smem round trip).
// ---------------------------------------------------------------------------
__global__ __launch_bounds__(TPB_E, 1)
void edge_mlp_kernel(const float* __restrict__ ef,
                     const float* __restrict__ mW1,
                     const float* __restrict__ mW2, const float* __restrict__ mb2,
                     const float* __restrict__ mW3, const float* __restrict__ mb3,
                     const int*   __restrict__ eidx,
                     float* __restrict__ agg)
{
    extern __shared__ char smem[];
    const int tid  = threadIdx.x;
    const int w    = tid >> 5;
    const int lane = tid & 31;
    const int m    = lane & 3;
    const int qrow = lane >> 2;

    STAGE_FRAGS1(OFF_W1, 2, 8, KR_W1E, mW1, 128, TPB_E)
    STAGE_FRAGS1(OFF_W2, 8, 8, KR_ID,  mW2, 128, TPB_E)
    STAGE_FRAGS1(OFF_W3, 8, 4, KR_ID,  mW3, 64,  TPB_E)
    float* b2s = (float*)(smem + OFF_B2);
    float* b3s = (float*)(smem + OFF_B3);
    if (tid < 128) b2s[tid] = mb2[tid];
    if (tid < 64)  b3s[tid] = mb3[tid];
    __syncthreads();

    uint32_t* pq16 = (uint32_t*)(smem + OFF_SC) + w * SC_WARP_U32;  // [16][68] u32

    const int gw = blockIdx.x * NW_E + w;
    const int gstride = gridDim.x * NW_E;

    for (int wt = gw; wt < N_WT_EDGE; wt += gstride) {
        const int base_e = wt * 16;

        int2 se = make_int2(0, 0);
        if (lane < 16) se = ((const int2*)eidx)[base_e + lane];
        __syncwarp();    // scratch reuse fence from previous tile

        // ---- prefetch ef (K=32) ----
        const float* e0p = ef + (size_t)(base_e + qrow) * 32;
        const float* e1p = ef + (size_t)(base_e + qrow + 8) * 32;
        float2 v00 = __ldg((const float2*)(e0p + 2 * m));
        float2 v01 = __ldg((const float2*)(e0p + 2 * m + 8));
        float2 v02 = __ldg((const float2*)(e0p + 2 * m + 16));
        float2 v03 = __ldg((const float2*)(e0p + 2 * m + 24));
        float2 v10 = __ldg((const float2*)(e1p + 2 * m));
        float2 v11 = __ldg((const float2*)(e1p + 2 * m + 8));
        float2 v12 = __ldg((const float2*)(e1p + 2 * m + 16));
        float2 v13 = __ldg((const float2*)(e1p + 2 * m + 24));

        // ---- stage PQ = Ph[src] (+b1 folded) + Qh[dst], pure half2 adds ----
        #pragma unroll 4
        for (int r = 0; r < 16; r++) {
            int sr = __shfl_sync(0xffffffffu, se.x, r);
            int dr = __shfl_sync(0xffffffffu, se.y, r);
            uint2 pv = __ldg((const uint2*)g_Ph + (size_t)sr * 32 + lane);
            uint2 qv = __ldg((const uint2*)g_Qh + (size_t)dr * 32 + lane);
            uint2 o;
            o.x = hadd2u(pv.x, qv.x);
            o.y = hadd2u(pv.y, qv.y);
            *(uint2*)(pq16 + r * PQ_STRIDE_U32 + 2 * lane) = o;
        }
        __syncwarp();

        // ---- A1 fragments (fp16) ----
        uint32_t A1[2][4];
        A1[0][0] = hpack2(v00.x, v00.y);
        A1[0][1] = hpack2(v10.x, v10.y);
        A1[0][2] = hpack2(v01.x, v01.y);
        A1[0][3] = hpack2(v11.x, v11.y);
        A1[1][0] = hpack2(v02.x, v02.y);
        A1[1][1] = hpack2(v12.x, v12.y);
        A1[1][2] = hpack2(v03.x, v03.y);
        A1[1][3] = hpack2(v13.x, v13.y);

        // ---- L1: C init = PQ (fp16->fp32); += ef@W1e (1 pass); -> A2 ----
        uint32_t A2[8][4];
        #pragma unroll
        for (int j = 0; j < 4; j++) {
            int j2 = j + 4;
            float Ca[4], Cb[4], Cc[4], Cd[4];
            {
                float2 a0 = hunpack2(pq16[qrow * PQ_STRIDE_U32 + 8 * j + m]);
                float2 a1 = hunpack2(pq16[(qrow + 8) * PQ_STRIDE_U32 + 8 * j + m]);
                float2 b0 = hunpack2(pq16[qrow * PQ_STRIDE_U32 + 8 * j + 4 + m]);
                float2 b1 = hunpack2(pq16[(qrow + 8) * PQ_STRIDE_U32 + 8 * j + 4 + m]);
                float2 c0 = hunpack2(pq16[qrow * PQ_STRIDE_U32 + 8 * j2 + m]);
                float2 c1 = hunpack2(pq16[(qrow + 8) * PQ_STRIDE_U32 + 8 * j2 + m]);
                float2 d0 = hunpack2(pq16[qrow * PQ_STRIDE_U32 + 8 * j2 + 4 + m]);
                float2 d1 = hunpack2(pq16[(qrow + 8) * PQ_STRIDE_U32 + 8 * j2 + 4 + m]);
                Ca[0] = a0.x; Ca[1] = a0.y; Ca[2] = a1.x; Ca[3] = a1.y;
                Cb[0] = b0.x; Cb[1] = b0.y; Cb[2] = b1.x; Cb[3] = b1.y;
                Cc[0] = c0.x; Cc[1] = c0.y; Cc[2] = c1.x; Cc[3] = c1.y;
                Cd[0] = d0.x; Cd[1] = d0.y; Cd[2] = d1.x; Cd[3] = d1.y;
            }
            #pragma unroll
            for (int kc = 0; kc < 2; kc++) {
                uint4 u = *(const uint4*)(smem + OFF_W1 + (((kc * 8 + j) * 32) + lane) * 16);
                uint4 v = *(const uint4*)(smem + OFF_W1 + (((kc * 8 + j2) * 32) + lane) * 16);
                mma_f16(Ca, A1[kc], u.x, u.y);
                mma_f16(Cb, A1[kc], u.z, u.w);
                mma_f16(Cc, A1[kc], v.x, v.y);
                mma_f16(Cd, A1[kc], v.z, v.w);
            }
            A2[j][0]  = hpack2(fmaxf(Ca[0], 0.f), fmaxf(Ca[1], 0.f));
            A2[j][1]  = hpack2(fmaxf(Ca[2], 0.f), fmaxf(Ca[3], 0.f));
            A2[j][2]  = hpack2(fmaxf(Cb[0], 0.f), fmaxf(Cb[1], 0.f));
            A2[j][3]  = hpack2(fmaxf(Cb[2], 0.f), fmaxf(Cb[3], 0.f));
            A2[j2][0] = hpack2(fmaxf(Cc[0], 0.f), fmaxf(Cc[1], 0.f));
            A2[j2][1] = hpack2(fmaxf(Cc[2], 0.f), fmaxf(Cc[3], 0.f));
            A2[j2][2] = hpack2(fmaxf(Cd[0], 0.f), fmaxf(Cd[1], 0.f));
            A2[j2][3] = hpack2(fmaxf(Cd[2], 0.f), fmaxf(Cd[3], 0.f));
        }

        // ---- L2: C init = b2; += h1@W2 (1 pass); -> A3 ----
        uint32_t A3[8][4];
        #pragma unroll
        for (int j = 0; j < 4; j++) {
            int j2 = j + 4;
            float Ca[4], Cb[4], Cc[4], Cd[4];
            {
                float2 ba2 = *(const float2*)(b2s + (2 * j) * 8 + 2 * m);
                float2 bb2 = *(const float2*)(b2s + (2 * j + 1) * 8 + 2 * m);
                float2 bc2 = *(const float2*)(b2s + (2 * j2) * 8 + 2 * m);
                float2 bd2 = *(const float2*)(b2s + (2 * j2 + 1) * 8 + 2 * m);
                Ca[0] = ba2.x; Ca[1] = ba2.y; Ca[2] = ba2.x; Ca[3] = ba2.y;
                Cb[0] = bb2.x; Cb[1] = bb2.y; Cb[2] = bb2.x; Cb[3] = bb2.y;
                Cc[0] = bc2.x; Cc[1] = bc2.y; Cc[2] = bc2.x; Cc[3] = bc2.y;
                Cd[0] = bd2.x; Cd[1] = bd2.y; Cd[2] = bd2.x; Cd[3] = bd2.y;
            }
            #pragma unroll
            for (int kc = 0; kc < 8; kc++) {
                uint4 u = *(const uint4*)(smem + OFF_W2 + (((kc * 8 + j) * 32) + lane) * 16);
                uint4 v = *(const uint4*)(smem + OFF_W2 + (((kc * 8 + j2) * 32) + lane) * 16);
                mma_f16(Ca, A2[kc], u.x, u.y);
                mma_f16(Cb, A2[kc], u.z, u.w);
                mma_f16(Cc, A2[kc], v.x, v.y);
                mma_f16(Cd, A2[kc], v.z, v.w);
            }
            A3[j][0]  = hpack2(fmaxf(Ca[0], 0.f), fmaxf(Ca[1], 0.f));
            A3[j][1]  = hpack2(fmaxf(Ca[2], 0.f), fmaxf(Ca[3], 0.f));
            A3[j][2]  = hpack2(fmaxf(Cb[0], 0.f), fmaxf(Cb[1], 0.f));
            A3[j][3]  = hpack2(fmaxf(Cb[2], 0.f), fmaxf(Cb[3], 0.f));
            A3[j2][0] = hpack2(fmaxf(Cc[0], 0.f), fmaxf(Cc[1], 0.f));
            A3[j2][1] = hpack2(fmaxf(Cc[2], 0.f), fmaxf(Cc[3], 0.f));
            A3[j2][2] = hpack2(fmaxf(Cd[0], 0.f), fmaxf(Cd[1], 0.f));
            A3[j2][3] = hpack2(fmaxf(Cd[2], 0.f), fmaxf(Cd[3], 0.f));
        }

        // ---- L3: C init = b3; += h2@W3 (1 pass); direct float2 atomics ----
        const int dn0 = __shfl_sync(0xffffffffu, se.y, qrow);
        const int dn1 = __shfl_sync(0xffffffffu, se.y, qrow + 8);
        float* agg0 = agg + (size_t)dn0 * 64 + 2 * m;
        float* agg1 = agg + (size_t)dn1 * 64 + 2 * m;
        #pragma unroll
        for (int t = 0; t < 2; t++) {
            int p0 = 2 * t, p1 = 2 * t + 1;
            float Ca[4], Cb[4], Cc[4], Cd[4];
            {
                float2 b0v = *(const float2*)(b3s + (4 * t) * 8 + 2 * m);
                float2 b1v = *(const float2*)(b3s + (4 * t + 1) * 8 + 2 * m);
                float2 b2v = *(const float2*)(b3s + (4 * t + 2) * 8 + 2 * m);
                float2 b3v = *(const float2*)(b3s + (4 * t + 3) * 8 + 2 * m);
                Ca[0] = b0v.x; Ca[1] = b0v.y; Ca[2] = b0v.x; Ca[3] = b0v.y;
                Cb[0] = b1v.x; Cb[1] = b1v.y; Cb[2] = b1v.x; Cb[3] = b1v.y;
                Cc[0] = b2v.x; Cc[1] = b2v.y; Cc[2] = b2v.x; Cc[3] = b2v.y;
                Cd[0] = b3v.x; Cd[1] = b3v.y; Cd[2] = b3v.x; Cd[3] = b3v.y;
            }
            #pragma unroll
            for (int kc = 0; kc < 8; kc++) {
                uint4 u = *(const uint4*)(smem + OFF_W3 + (((kc * 4 + p0) * 32) + lane) * 16);
                uint4 v = *(const uint4*)(smem + OFF_W3 + (((kc * 4 + p1) * 32) + lane) * 16);
                mma_f16(Ca, A3[kc], u.x, u.y);
                mma_f16(Cb, A3[kc], u.z, u.w);
                mma_f16(Cc, A3[kc], v.x, v.y);
                mma_f16(Cd, A3[kc], v.z, v.w);
            }
            atomicAdd((float2*)(agg0 + 8 * (4 * t)),     make_float2(Ca[0], Ca[1]));
            atomicAdd((float2*)(agg1 + 8 * (4 * t)),     make_float2(Ca[2], Ca[3]));
            atomicAdd((float2*)(agg0 + 8 * (4 * t + 1)), make_float2(Cb[0], Cb[1]));
            atomicAdd((float2*)(agg1 + 8 * (4 * t + 1)), make_float2(Cb[2], Cb[3]));
            atomicAdd((float2*)(agg0 + 8 * (4 * t + 2)), make_float2(Cc[0], Cc[1]));
            atomicAdd((float2*)(agg1 + 8 * (4 * t + 2)), make_float2(Cc[2], Cc[3]));
            atomicAdd((float2*)(agg0 + 8 * (4 * t + 3)), make_float2(Cd[0], Cd[1]));
            atomicAdd((float2*)(agg1 + 8 * (4 * t + 3)), make_float2(Cd[2], Cd[3]));
        }
    }
}

extern "C" void kernel_launch(void* const* d_in, const int* in_sizes, int n_in,
                              void* d_out, int out_size)
{
    const float* nf  = (const float*)d_in[0];
    const float* ef  = (const float*)d_in[1];
    const float* stx = (const float*)d_in[2];
    const float* mW1 = (const float*)d_in[3];
    const float* mb1 = (const float*)d_in[4];
    const float* mW2 = (const float*)d_in[5];
    const float* mb2 = (const float*)d_in[6];
    const float* mW3 = (const float*)d_in[7];
    const float* mb3 = (const float*)d_in[8];
    const float* uW1 = (const float*)d_in[9];
    const float* ub1 = (const float*)d_in[10];
    const float* uW2 = (const float*)d_in[11];
    const float* ub2 = (const float*)d_in[12];
    const int*  eidx = (const int*)d_in[13];

    float* out_node = (float*)d_out;
    float* agg      = out_node + (size_t)N_NODES_C * 64;

    cudaFuncSetAttribute(edge_mlp_kernel,
                         cudaFuncAttributeMaxDynamicSharedMemorySize, EDGE_SMEM_BYTES);
    cudaFuncSetAttribute(node_fused_kernel,
                         cudaFuncAttributeMaxDynamicSharedMemorySize, NODEF_SMEM_BYTES);

    int dev = 0;
    cudaGetDevice(&dev);
    int sms = 148;
    cudaDeviceGetAttribute(&sms, cudaDevAttrMultiProcessorCount, dev);

    node_fused_kernel<<<sms, TPB_N, NODEF_SMEM_BYTES>>>(nf, stx, mW1, mb1, uW1, ub1,
                                                        uW2, ub2, out_node, agg);
    edge_mlp_kernel<<<sms, TPB_E, EDGE_SMEM_BYTES>>>(ef, mW1, mW2, mb2,
                                                     mW3, mb3, eidx, agg);
}